// round 14
// baseline (speedup 1.0000x reference)
#include <cuda_runtime.h>

#define Bv 128
#define Tv 1024
#define Nv 64
#define U 8
#define TPB 128

// Scratch (no cudaMalloc allowed). g_ctr wraps back to 0 every full run -> graph-safe.
__device__ float g_loss[Bv];
__device__ unsigned g_ctr = 0;

#define FMA_X2(d, a, b, c) \
  asm("fma.rn.f32x2 %0, %1, %2, %3;" : "=l"(d) : "l"(a), "l"(b), "l"(c))
#define ADD_X2(d, a, b) \
  asm("add.rn.f32x2 %0, %1, %2;" : "=l"(d) : "l"(a), "l"(b))

__global__ __launch_bounds__(TPB) void crf_kernel(
    const float* __restrict__ pot, const int* __restrict__ tags,
    const int* __restrict__ seqlen, const float* __restrict__ K,
    const float* __restrict__ w, float* __restrict__ out) {
  const int b = blockIdx.x;
  const int j = threadIdx.x;           // 0..127
  const int jj = j & 63;               // state (h-major layout: warps 0-1 h=0)
  const int h = j >> 6;                // i-half
  const int wid = j >> 5, lane = j & 31;
  const int L = seqlen[b];

  __shared__ float Ksh[Nv * 65];                 // padded
  __shared__ __align__(16) float slots[3][Nv];   // 3-slot rotation: read/RED/zero
  __shared__ float sbase;
  __shared__ float redx[4], redm2[4];
  __shared__ int slast;

  const float* potb = pot + (long)b * Tv * Nv;
  const int* tagb = tags + b * Tv;

  for (int idx = j; idx < Nv * Nv; idx += TPB) {
    int row = idx >> 6, col = idx & 63;
    Ksh[row * 65 + col] = K[idx];
  }
  __syncthreads();

  // ---- sequence score: batched loads for MLP (t = j + 128u <= 1023 in-bounds) ----
  int tg[8], tp[8];
#pragma unroll
  for (int u = 0; u < 8; u++) {
    int t = j + TPB * u;
    tg[u] = tagb[t];
    tp[u] = tagb[t > 0 ? t - 1 : 0];
  }
  float pv[8];
#pragma unroll
  for (int u = 0; u < 8; u++) pv[u] = potb[(j + TPB * u) * Nv + tg[u]];
  float sc = 0.f;
#pragma unroll
  for (int u = 0; u < 8; u++) {
    int t = j + TPB * u;
    if (t < L) {
      sc += pv[u];
      if (t >= 1) sc += Ksh[tp[u] * 65 + tg[u]];
    }
  }
#pragma unroll
  for (int o = 16; o > 0; o >>= 1) sc += __shfl_xor_sync(0xffffffffu, sc, o);
  if (lane == 0) redx[wid] = sc;

  // ---- exp(K) for column jj, i-range [32h, 32h+32), 16 packed regs ----
  unsigned long long eK2[16];
#pragma unroll
  for (int p = 0; p < 16; p++) {
    int row = 32 * h + 2 * p;
    float e0 = __expf(Ksh[row * 65 + jj]);
    float e1 = __expf(Ksh[(row + 1) * 65 + jj]);
    asm("mov.b64 %0, {%1, %2};" : "=l"(eK2[p]) : "f"(e0), "f"(e1));
  }

  // ---- init t = 0: slot0 = f_0 = exp(pot0 - C0), slot1 = 0 (RED target of step 1) ----
  float a0v = potb[jj];
  if (j == 0) sbase = a0v;
  float pc[U], pn[U];
#pragma unroll
  for (int u = 0; u < U; u++) {          // pot rows for t = 1..U (clamped)
    int t = 1 + u; if (t > L - 1) t = L - 1;
    pc[u] = potb[t * Nv + jj];
  }
  __syncthreads();
  float sscore = (redx[0] + redx[1]) + (redx[2] + redx[3]);
  float C0 = sbase;
  if (h == 0) {
    slots[0][jj] = __expf(a0v - C0);
    slots[1][jj] = 0.f;
  }
  float acc = C0 * 1.4426950408889634f;  // running -log2(c_t); exact from here on
  __syncthreads();

  // ---- main scan. Split-K: thread (h,jj) does 16 packed FMAs over its i-half,
  //      folds x pr, atomicAdd-combines into slot w (zeroed one step ahead).
  //      One barrier per step; 3-slot rotation avoids a zeroing barrier. ----
  float* sR = slots[0];                  // holds f_{t-1}
  float* sW = slots[1];                  // RED target for f_t (pre-zeroed)
  float* sZ = slots[2];                  // zeroed this step, RED target next step
  for (int tb = 1; tb < L; tb += U) {
    const int nb = tb + U;
#pragma unroll
    for (int u = 0; u < U; u++) {        // prefetch next chunk (clamped, branch-free)
      int t = nb + u; if (t > L - 1) t = L - 1;
      pn[u] = potb[t * Nv + jj];
    }
    float ec[U];                          // p_t = exp(pot) for this chunk (off-chain)
#pragma unroll
    for (int u = 0; u < U; u++) ec[u] = __expf(pc[u]);
#pragma unroll
    for (int u = 0; u < U; u++) {
      const int tt = tb + u;
      if (tt >= L) break;                // uniform across block

      if (h == 0) sZ[jj] = 0.f;          // prep RED target for step t+1 (off-chain)

      // power-of-2 normalizer from f_{t-1,0} exponent bits (exact, no MUFU)
      float f0 = sR[0];                  // broadcast LDS
      unsigned eb = __float_as_uint(f0) & 0x7F800000u;
      float rsc = __uint_as_float(0x7F000000u - eb);   // 2^-(E-127)
      acc += (float)(int)(eb >> 23) - 127.0f;
      float pr = ec[u] * rsc;

      // partial dot over i in [32h, 32h+32): 8 x LDS.128 (broadcast per warp)
      const ulonglong2* e2 = (const ulonglong2*)sR + 8 * h;
      unsigned long long a4[4] = {0ull, 0ull, 0ull, 0ull};
#pragma unroll
      for (int q = 0; q < 8; q++) {      // 16 packed FMAs = 32 scalar MACs
        ulonglong2 v = e2[q];
        FMA_X2(a4[(2 * q) & 3], v.x, eK2[2 * q], a4[(2 * q) & 3]);
        FMA_X2(a4[(2 * q + 1) & 3], v.y, eK2[2 * q + 1], a4[(2 * q + 1) & 3]);
      }
      unsigned long long t01, t23, sA;
      ADD_X2(t01, a4[0], a4[1]);
      ADD_X2(t23, a4[2], a4[3]);
      ADD_X2(sA, t01, t23);
      float slo, shi;
      asm("mov.b64 {%0, %1}, %2;" : "=f"(slo), "=f"(shi) : "l"(sA));
      float part = (slo + shi) * pr;     // my half of f_t,jj (pr folded pre-RED)

      atomicAdd(&sW[jj], part);          // 2-way combine; IEEE add commutative ->
                                         // deterministic; drained by the barrier
      float* tmp = sR; sR = sW; sW = sZ; sZ = tmp;   // rotate (r,w,z) <- (w,z,r)
      __syncthreads();
    }
#pragma unroll
    for (int u = 0; u < U; u++) pc[u] = pn[u];
  }

  // ---- finish: f_{L-1} now lives in sR. logZ = ln2 * (acc + log2(sum_j f)) ----
  float se = (h == 0) ? sR[jj] : 0.f;
#pragma unroll
  for (int o = 16; o > 0; o >>= 1) se += __shfl_xor_sync(0xffffffffu, se, o);
  if (lane == 0) redm2[wid] = se;
  __syncthreads();

  if (j == 0) {
    float sumf = (redm2[0] + redm2[1]) + (redm2[2] + redm2[3]);
    float logZ = 0.6931471805599453f * (acc + __log2f(sumf));
    g_loss[b] = -(sscore - logZ) * w[b];
    __threadfence();
    unsigned old = atomicInc(&g_ctr, Bv - 1);  // wraps to 0 each full run
    slast = (old == (unsigned)(Bv - 1)) ? 1 : 0;
  }
  __syncthreads();
  if (slast) {
    float v = __ldcg(&g_loss[j]);        // TPB == Bv: one element per thread
#pragma unroll
    for (int o = 16; o > 0; o >>= 1) v += __shfl_xor_sync(0xffffffffu, v, o);
    if (lane == 0) redx[wid] = v;
    __syncthreads();
    if (j == 0)
      out[0] = ((redx[0] + redx[1]) + (redx[2] + redx[3])) * (1.0f / (float)Bv);
  }
}

extern "C" void kernel_launch(void* const* d_in, const int* in_sizes, int n_in,
                              void* d_out, int out_size) {
  const float* pot    = (const float*)d_in[0];  // [128,1024,64] f32
  const int*   tags   = (const int*)  d_in[1];  // [128,1024] i32
  const int*   seqlen = (const int*)  d_in[2];  // [128] i32
  const float* K      = (const float*)d_in[3];  // [64,64] f32
  const float* w      = (const float*)d_in[4];  // [128] f32
  crf_kernel<<<Bv, TPB>>>(pot, tags, seqlen, K, w, (float*)d_out);
}

// round 15
// speedup vs baseline: 1.7425x; 1.7425x over previous
#include <cuda_runtime.h>

#define Bv 128
#define Tv 1024
#define Nv 64
#define U 8

// Scratch (no cudaMalloc allowed). g_ctr wraps back to 0 every full run -> graph-safe.
__device__ float g_loss[Bv];
__device__ unsigned g_ctr = 0;

#define FMA_X2(d, a, b, c) \
  asm("fma.rn.f32x2 %0, %1, %2, %3;" : "=l"(d) : "l"(a), "l"(b), "l"(c))
#define ADD_X2(d, a, b) \
  asm("add.rn.f32x2 %0, %1, %2;" : "=l"(d) : "l"(a), "l"(b))

__global__ __launch_bounds__(64) void crf_kernel(
    const float* __restrict__ pot, const int* __restrict__ tags,
    const int* __restrict__ seqlen, const float* __restrict__ K,
    const float* __restrict__ w, float* __restrict__ out) {
  const int b = blockIdx.x;
  const int j = threadIdx.x;           // state 0..63
  const int wid = j >> 5, lane = j & 31;
  const int L = seqlen[b];

  __shared__ float Ksh[Nv * 65];                 // padded for column reads
  __shared__ __align__(16) float fbuf[2][Nv];    // ping-pong scaled forward vector f
  __shared__ float sbase;                        // C0 broadcast
  __shared__ float redx[2], redm2[2];
  __shared__ int slast;

  const float* potb = pot + (long)b * Tv * Nv;
  const int* tagb = tags + b * Tv;

  for (int i = 0; i < Nv; i++) Ksh[i * 65 + j] = K[i * Nv + j];
  __syncthreads();

  // ---- sequence score: batched loads for MLP (t = j + 64u <= 1023 in-bounds) ----
  int tg[16], tp[16];
#pragma unroll
  for (int u = 0; u < 16; u++) {
    int t = j + 64 * u;
    tg[u] = tagb[t];
    tp[u] = tagb[t > 0 ? t - 1 : 0];
  }
  float pv[16];
#pragma unroll
  for (int u = 0; u < 16; u++) pv[u] = potb[(j + 64 * u) * Nv + tg[u]];
  float sc = 0.f;
#pragma unroll
  for (int u = 0; u < 16; u++) {
    int t = j + 64 * u;
    if (t < L) {
      sc += pv[u];
      if (t >= 1) sc += Ksh[tp[u] * 65 + tg[u]];
    }
  }
#pragma unroll
  for (int o = 16; o > 0; o >>= 1) sc += __shfl_xor_sync(0xffffffffu, sc, o);
  if (lane == 0) redx[wid] = sc;

  // ---- exp(K) column j, packed f32x2 pairs along i ----
  unsigned long long eK2[32];
#pragma unroll
  for (int p = 0; p < 32; p++) {
    float e0 = __expf(Ksh[(2 * p) * 65 + j]);
    float e1 = __expf(Ksh[(2 * p + 1) * 65 + j]);
    asm("mov.b64 %0, {%1, %2};" : "=l"(eK2[p]) : "f"(e0), "f"(e1));
  }

  // ---- init t = 0: f0 = exp(pot0 - C0), C0 = pot[0][0] (=> f_{0,0} = 1) ----
  float a0 = potb[j];
  if (j == 0) sbase = a0;
  float pc[U];
#pragma unroll
  for (int u = 0; u < U; u++) {          // raw pot rows for t = 1..U (L >= 512 > 9)
    pc[u] = potb[(1 + u) * Nv + j];
  }
  __syncthreads();
  float sscore = redx[0] + redx[1];
  float C0 = sbase;
  float fj = __expf(a0 - C0);            // thread-local last f value
  fbuf[1][j] = fj;
  float acc = C0 * 1.4426950408889634f;  // running -log2(c_t); exact from here on
  __syncthreads();

  // ================= main scan: FULL chunks, zero per-step branches =================
  // Chain: BAR -> LDS -> 32 packed FMA -> tree -> mul -> STS. Normalizer is a
  // power of two from f_{t-1,0}'s exponent bits (pure ALU, exact).
  int tb = 1;
  for (; tb + U <= L; tb += U) {
    float ec[U];                          // p_t = exp(pot) (burst; results used >=16cyc later)
#pragma unroll
    for (int u = 0; u < U; u++) ec[u] = __expf(pc[u]);
#pragma unroll
    for (int u = 0; u < U; u++) {
      // one prefetch LDG per step (pc[u] free once ec[u] extracted)
      int tn = tb + U + u; if (tn > L - 1) tn = L - 1;
      pc[u] = potb[tn * Nv + j];

      const int rb = (1 + u) & 1, wb = rb ^ 1;   // tb always odd -> compile-time
      const ulonglong2* e2 = (const ulonglong2*)fbuf[rb];

      ulonglong2 v0 = e2[0];
      float f0, f1d;
      asm("mov.b64 {%0, %1}, %2;" : "=f"(f0), "=f"(f1d) : "l"(v0.x));
      unsigned eb = __float_as_uint(f0) & 0x7F800000u;
      float r = __uint_as_float(0x7F000000u - eb);       // 2^-(E-127), exact
      acc += (float)(int)(eb >> 23) - 127.0f;            // k, exact
      float pr = ec[u] * r;

      unsigned long long a4[4] = {0ull, 0ull, 0ull, 0ull};
      FMA_X2(a4[0], v0.x, eK2[0], a4[0]);
      FMA_X2(a4[1], v0.y, eK2[1], a4[1]);
#pragma unroll
      for (int q = 1; q < 16; q++) {     // remaining 30 packed FMAs, 4 chains
        ulonglong2 v = e2[q];
        FMA_X2(a4[(2 * q) & 3], v.x, eK2[2 * q], a4[(2 * q) & 3]);
        FMA_X2(a4[(2 * q + 1) & 3], v.y, eK2[2 * q + 1], a4[(2 * q + 1) & 3]);
      }
      unsigned long long t01, t23, sA;
      ADD_X2(t01, a4[0], a4[1]);
      ADD_X2(t23, a4[2], a4[3]);
      ADD_X2(sA, t01, t23);
      float slo, shi;
      asm("mov.b64 {%0, %1}, %2;" : "=f"(slo), "=f"(shi) : "l"(sA));
      float s = slo + shi;

      fj = s * pr;                       // f_t,j
      fbuf[wb][j] = fj;
      __syncthreads();
    }
  }

  // ================= tail: < U steps, break-style (runs once) =================
#pragma unroll
  for (int u = 0; u < U; u++) {
    const int tt = tb + u;
    if (tt >= L) break;                  // uniform across block
    const int rb = tt & 1, wb = rb ^ 1;
    float ecs = __expf(pc[u]);
    const ulonglong2* e2 = (const ulonglong2*)fbuf[rb];

    ulonglong2 v0 = e2[0];
    float f0, f1d;
    asm("mov.b64 {%0, %1}, %2;" : "=f"(f0), "=f"(f1d) : "l"(v0.x));
    unsigned eb = __float_as_uint(f0) & 0x7F800000u;
    float r = __uint_as_float(0x7F000000u - eb);
    acc += (float)(int)(eb >> 23) - 127.0f;
    float pr = ecs * r;

    unsigned long long a4[4] = {0ull, 0ull, 0ull, 0ull};
    FMA_X2(a4[0], v0.x, eK2[0], a4[0]);
    FMA_X2(a4[1], v0.y, eK2[1], a4[1]);
#pragma unroll
    for (int q = 1; q < 16; q++) {
      ulonglong2 v = e2[q];
      FMA_X2(a4[(2 * q) & 3], v.x, eK2[2 * q], a4[(2 * q) & 3]);
      FMA_X2(a4[(2 * q + 1) & 3], v.y, eK2[2 * q + 1], a4[(2 * q + 1) & 3]);
    }
    unsigned long long t01, t23, sA;
    ADD_X2(t01, a4[0], a4[1]);
    ADD_X2(t23, a4[2], a4[3]);
    ADD_X2(sA, t01, t23);
    float slo, shi;
    asm("mov.b64 {%0, %1}, %2;" : "=f"(slo), "=f"(shi) : "l"(sA));
    float s = slo + shi;

    fj = s * pr;
    fbuf[wb][j] = fj;
    __syncthreads();
  }

  // ---- finish: logZ = ln2 * (acc + log2(sum_j f_{L-1,j})) ----
  float se = fj;
#pragma unroll
  for (int o = 16; o > 0; o >>= 1) se += __shfl_xor_sync(0xffffffffu, se, o);
  if (lane == 0) redm2[wid] = se;
  __syncthreads();

  if (j == 0) {
    float sumf = redm2[0] + redm2[1];
    float logZ = 0.6931471805599453f * (acc + __log2f(sumf));
    g_loss[b] = -(sscore - logZ) * w[b];
    __threadfence();
    unsigned old = atomicInc(&g_ctr, Bv - 1);  // wraps to 0 each full run
    slast = (old == (unsigned)(Bv - 1)) ? 1 : 0;
  }
  __syncthreads();
  if (slast) {
    float v = __ldcg(&g_loss[j]) + __ldcg(&g_loss[j + 64]);
#pragma unroll
    for (int o = 16; o > 0; o >>= 1) v += __shfl_xor_sync(0xffffffffu, v, o);
    if (lane == 0) redx[wid] = v;
    __syncthreads();
    if (j == 0) out[0] = (redx[0] + redx[1]) * (1.0f / (float)Bv);
  }
}

extern "C" void kernel_launch(void* const* d_in, const int* in_sizes, int n_in,
                              void* d_out, int out_size) {
  const float* pot    = (const float*)d_in[0];  // [128,1024,64] f32
  const int*   tags   = (const int*)  d_in[1];  // [128,1024] i32
  const int*   seqlen = (const int*)  d_in[2];  // [128] i32
  const float* K      = (const float*)d_in[3];  // [64,64] f32
  const float* w      = (const float*)d_in[4];  // [128] f32
  crf_kernel<<<Bv, Nv>>>(pot, tags, seqlen, K, w, (float*)d_out);
}